// round 2
// baseline (speedup 1.0000x reference)
#include <cuda_runtime.h>

#define THR 0.5f
#define MIN_JUMP_ENERGY 0.5f
#define MIN_VELOCITY_THRESHOLD 0.1f
#define MIN_WALL_JUMP_SPEED 1.0f

static constexpr int B = 32;
static constexpr int E = 100000;

__global__ __launch_bounds__(256) void edge_mask_kernel(
    const float4* __restrict__ feat,     // [B, E, 16] viewed as [B*E, 4] float4
    const float*  __restrict__ phys,     // [B, 18]
    const float*  __restrict__ base,     // [B, E]
    float*        __restrict__ out)      // [B, E]
{
    const int b = blockIdx.y;
    const int e = blockIdx.x * blockDim.x + threadIdx.x;
    if (e >= E) return;

    // Per-batch physics scalars (warp-uniform; L1-resident)
    const float* p = phys + b * 18;
    const float vel_magnitude = p[2];
    const float wall_contact  = p[5];
    const float kinetic_energy = p[9];
    const float can_jump      = p[16];
    const float can_wall_jump = p[17];

    const long long row = (long long)b * E + e;
    const float4* f = feat + row * 4;
    const float4 f0 = f[0];   // cols 0-3
    const float4 f1 = f[1];   // cols 4-7
    const float4 f2 = f[2];   // cols 8-11
    const float4 f3 = f[3];   // cols 12-15

    // argmax over cols 0..5, first-max-wins (strict >)
    int   et  = 0;
    float mx  = f0.x;
    if (f0.y > mx) { mx = f0.y; et = 1; }
    if (f0.z > mx) { mx = f0.z; et = 2; }
    if (f0.w > mx) { mx = f0.w; et = 3; }
    if (f1.x > mx) { mx = f1.x; et = 4; }
    if (f1.y > mx) { mx = f1.y; et = 5; }

    const float energy_cost           = f2.z;  // col 10
    const float min_velocity          = f3.x;  // col 12
    const float max_velocity          = f3.y;  // col 13
    const float requires_jump         = f3.z;  // col 14
    const float requires_wall_contact = f3.w;  // col 15

    // jnp.select: first-true-wins priority chain
    const bool c1 = (et == 1) && (can_jump < THR);
    const bool c2 = (et == 3);
    const bool d2 = (wall_contact < THR) || (vel_magnitude < MIN_VELOCITY_THRESHOLD);
    const bool c3 = (requires_jump > THR);
    const bool d3 = (can_jump < THR) || (vel_magnitude < min_velocity);
    const bool c4 = (requires_wall_contact > THR);
    const bool d4 = (wall_contact < THR) ||
                    ((can_wall_jump < THR) && (vel_magnitude < MIN_WALL_JUMP_SPEED));
    const bool c5 = (et == 1);
    const bool d5 = (kinetic_energy < energy_cost * MIN_JUMP_ENERGY);

    bool should_disable;
    if      (c1) should_disable = true;
    else if (c2) should_disable = d2;
    else if (c3) should_disable = d3;
    else if (c4) should_disable = d4;
    else if (c5) should_disable = d5;
    else         should_disable = false;

    const bool over  = (max_velocity > 0.0f) && (vel_magnitude > max_velocity);
    const bool under = (!over) && (vel_magnitude < min_velocity);
    should_disable = should_disable || over || under;

    out[row] = should_disable ? 0.0f : base[row];
}

extern "C" void kernel_launch(void* const* d_in, const int* in_sizes, int n_in,
                              void* d_out, int out_size)
{
    const float4* feat = (const float4*)d_in[0];
    const float*  phys = (const float*) d_in[1];
    const float*  base = (const float*) d_in[2];
    float*        out  = (float*)d_out;

    dim3 block(256);
    dim3 grid((E + 255) / 256, B);
    edge_mask_kernel<<<grid, block>>>(feat, phys, base, out);
}